// round 9
// baseline (speedup 1.0000x reference)
#include <cuda_runtime.h>
#include <math.h>
#include <float.h>

#define EPSV 1e-6f
#define SCALEV 0.125f   // 1/sqrt(64)

// Precomputed prototype-side constants
__device__ float d_gp[16 * 64];   // gp[k][d] = gamma0[d] * LN(proto_k)[d]
__device__ float d_sgp[16];       // sum_d gp[k][d]
__device__ float d_ck[16];        // sum_d beta0[d] * LN(proto_k)[d]

// ---------------------------------------------------------------------------
// Setup kernel: LN the prototypes, fold gamma0/beta0 into score constants.
// 16 warps, one per prototype row (D=64 -> 2 elems/lane).
// ---------------------------------------------------------------------------
__global__ void setup_kernel(const float* __restrict__ prot,
                             const float* __restrict__ gamma,
                             const float* __restrict__ beta)
{
    int w = threadIdx.x >> 5;
    int l = threadIdx.x & 31;
    if (w >= 16) return;
    const float* g0 = gamma;
    const float* b0 = beta;
    const float* g1 = gamma + 64;
    const float* b1 = beta + 64;

    float p0 = prot[w * 64 + l];
    float p1 = prot[w * 64 + l + 32];
    float s = p0 + p1, q = p0 * p0 + p1 * p1;
    #pragma unroll
    for (int m = 16; m; m >>= 1) {
        s += __shfl_xor_sync(~0u, s, m);
        q += __shfl_xor_sync(~0u, q, m);
    }
    float mean = s * (1.f / 64.f);
    float var  = q * (1.f / 64.f) - mean * mean;
    float r    = rsqrtf(var + EPSV);
    float pn0 = (p0 - mean) * r * g1[l]      + b1[l];
    float pn1 = (p1 - mean) * r * g1[l + 32] + b1[l + 32];
    float gp0 = g0[l] * pn0;
    float gp1 = g0[l + 32] * pn1;
    d_gp[w * 64 + l]      = gp0;
    d_gp[w * 64 + l + 32] = gp1;
    float sg  = gp0 + gp1;
    float ckp = b0[l] * pn0 + b0[l + 32] * pn1;
    #pragma unroll
    for (int m = 16; m; m >>= 1) {
        sg  += __shfl_xor_sync(~0u, sg, m);
        ckp += __shfl_xor_sync(~0u, ckp, m);
    }
    if (l == 0) { d_sgp[w] = sg; d_ck[w] = ckp; }
}

// ---------------------------------------------------------------------------
// Main kernel: one block per batch b. 256 threads, 16 tiles of 64 tokens.
// Single pass over z with online softmax over T fused into the aggregation.
// ---------------------------------------------------------------------------
__global__ __launch_bounds__(256, 3)
void dse_main_kernel(const float* __restrict__ z,
                     const float* __restrict__ alphas,
                     const float* __restrict__ b_bias,
                     const float* __restrict__ W,
                     const float* __restrict__ gamma,
                     const float* __restrict__ beta,
                     const float* __restrict__ beta_seq,
                     float* __restrict__ out)
{
    __shared__ __align__(16) float z_s[64 * 68];   // token tile [t][d], pad 68
    __shared__ __align__(16) float gp_s[16 * 68];  // gp, pad 68
    __shared__ __align__(16) float sw[64 * 16];    // per-tile weights w[t][k]
    __shared__ __align__(16) float sm_u[64];
    __shared__ float sm_m[64], sm_r[64];
    __shared__ float st_full[1024];                // scoreT logits (scaled)
    __shared__ float sm_q[64];
    __shared__ float sm_sgp[16], sm_ck[16];
    __shared__ float sm_su, sm_M, sm_fac, sm_S;
    __shared__ float sm_red[8];

    const int tid  = threadIdx.x;
    const int lane = tid & 31;
    const int wid  = tid >> 5;
    const int b    = blockIdx.x;
    const size_t zb = (size_t)b * (1024 * 64);

    // ---- prologue: warp0 builds q, q' = q + W q, u = g2*q', su ----
    if (wid == 0) {
        const float* g3 = gamma + 3 * 64;
        const float* b3 = beta  + 3 * 64;
        const float* g2 = gamma + 2 * 64;
        const int d1 = lane, d2 = lane + 32;
        float x1 = alphas[1023 * 64 + d1] + z[zb + 1023 * 64 + d1] + b_bias[d1];
        float x2 = alphas[1023 * 64 + d2] + z[zb + 1023 * 64 + d2] + b_bias[d2];
        float s = x1 + x2, sq = x1 * x1 + x2 * x2;
        #pragma unroll
        for (int m = 16; m; m >>= 1) {
            s  += __shfl_xor_sync(~0u, s,  m);
            sq += __shfl_xor_sync(~0u, sq, m);
        }
        float mean = s * (1.f / 64.f);
        float var  = sq * (1.f / 64.f) - mean * mean;
        float r    = rsqrtf(var + EPSV);
        float q1 = (x1 - mean) * r * g3[d1] + b3[d1];
        float q2 = (x2 - mean) * r * g3[d2] + b3[d2];
        sm_q[d1] = q1; sm_q[d2] = q2;
        __syncwarp();
        float wq1 = 0.f, wq2 = 0.f;
        #pragma unroll 4
        for (int e4 = 0; e4 < 16; e4++) {
            float4 qv = *(const float4*)&sm_q[e4 * 4];
            float4 w1 = *(const float4*)(W + d1 * 64 + e4 * 4);
            float4 w2 = *(const float4*)(W + d2 * 64 + e4 * 4);
            wq1 += w1.x * qv.x + w1.y * qv.y + w1.z * qv.z + w1.w * qv.w;
            wq2 += w2.x * qv.x + w2.y * qv.y + w2.z * qv.z + w2.w * qv.w;
        }
        float u1 = g2[d1] * (q1 + wq1);
        float u2 = g2[d2] * (q2 + wq2);
        sm_u[d1] = u1; sm_u[d2] = u2;
        float su = u1 + u2;
        #pragma unroll
        for (int m = 16; m; m >>= 1) su += __shfl_xor_sync(~0u, su, m);
        if (lane == 0) { sm_su = su; sm_M = -FLT_MAX; }
    } else {
        for (int i = tid - 32; i < 1024; i += 224)
            gp_s[(i >> 6) * 68 + (i & 63)] = d_gp[i];
        if (tid >= 32 && tid < 48) sm_sgp[tid - 32] = d_sgp[tid - 32];
        if (tid >= 48 && tid < 64) sm_ck[tid - 48]  = d_ck[tid - 48];
    }
    __syncthreads();

    // thread role mappings
    const int k    = tid & 15;          // GEMM/softmaxK: intent index
    const int tl   = tid >> 4;          // GEMM: row-within-subtile
    const int srow = tid >> 2;          // staging: row
    const int sc0  = (tid & 3) * 16;    // staging: col start
    const int kg   = tid >> 6;          // aggregation: k-group (4 k's)
    const int dd   = tid & 63;          // aggregation: dim

    const float sgp_k = sm_sgp[k];
    const float ck_k  = sm_ck[k];
    const float su    = sm_su;

    float a0 = 0.f, a1 = 0.f, a2 = 0.f, a3 = 0.f;  // out accumulators (4 k's, dim dd)

    for (int tile = 0; tile < 16; tile++) {
        const int tbase = tile * 64;

        // ---- stage tile + per-row stats + scoreT ----
        {
            const size_t zoff = zb + (size_t)(tbase + srow) * 64 + sc0;
            const size_t aoff = (size_t)(tbase + srow) * 64 + sc0;
            float4 zv[4], av[4];
            #pragma unroll
            for (int j = 0; j < 4; j++) zv[j] = *(const float4*)(z + zoff + 4 * j);
            #pragma unroll
            for (int j = 0; j < 4; j++) av[j] = *(const float4*)(alphas + aoff + 4 * j);

            float zs = 0, zq = 0, xs = 0, xq = 0, xu = 0;
            #pragma unroll
            for (int j = 0; j < 4; j++) {
                float4 uz = *(const float4*)&sm_u[sc0 + 4 * j];
                float4 zz = zv[j];
                float xx0 = zz.x + av[j].x, xx1 = zz.y + av[j].y;
                float xx2 = zz.z + av[j].z, xx3 = zz.w + av[j].w;
                zs += zz.x + zz.y + zz.z + zz.w;
                zq += zz.x * zz.x + zz.y * zz.y + zz.z * zz.z + zz.w * zz.w;
                xs += xx0 + xx1 + xx2 + xx3;
                xq += xx0 * xx0 + xx1 * xx1 + xx2 * xx2 + xx3 * xx3;
                xu += xx0 * uz.x + xx1 * uz.y + xx2 * uz.z + xx3 * uz.w;
                *(float4*)&z_s[srow * 68 + sc0 + 4 * j] = zz;
            }
            #pragma unroll
            for (int m = 1; m < 4; m <<= 1) {
                zs += __shfl_xor_sync(~0u, zs, m);
                zq += __shfl_xor_sync(~0u, zq, m);
                xs += __shfl_xor_sync(~0u, xs, m);
                xq += __shfl_xor_sync(~0u, xq, m);
                xu += __shfl_xor_sync(~0u, xu, m);
            }
            if ((tid & 3) == 0) {
                float mz = zs * (1.f / 64.f);
                float vz = zq * (1.f / 64.f) - mz * mz;
                sm_m[srow] = mz;
                sm_r[srow] = rsqrtf(vz + EPSV);
                float mx = xs * (1.f / 64.f);
                float vx = xq * (1.f / 64.f) - mx * mx;
                float rx = rsqrtf(vx + EPSV);
                st_full[tbase + srow] = SCALEV * (rx * (xu - mx * su));
            }
        }
        __syncthreads();

        // ---- warp0: running-max update; all threads: scoresK GEMM ----
        if (wid == 0) {
            float v = fmaxf(st_full[tbase + lane], st_full[tbase + lane + 32]);
            #pragma unroll
            for (int m = 16; m; m >>= 1) v = fmaxf(v, __shfl_xor_sync(~0u, v, m));
            if (lane == 0) {
                float Mold = sm_M;
                float Mn   = fmaxf(Mold, v);
                sm_fac = __expf(Mold - Mn);
                sm_M   = Mn;
            }
        }
        float raw0 = 0, raw1 = 0, raw2 = 0, raw3 = 0;
        #pragma unroll
        for (int d4 = 0; d4 < 16; d4++) {
            float4 g  = *(const float4*)&gp_s[k * 68 + d4 * 4];
            float4 z0 = *(const float4*)&z_s[(0 * 16 + tl) * 68 + d4 * 4];
            float4 z1 = *(const float4*)&z_s[(1 * 16 + tl) * 68 + d4 * 4];
            float4 z2 = *(const float4*)&z_s[(2 * 16 + tl) * 68 + d4 * 4];
            float4 z3 = *(const float4*)&z_s[(3 * 16 + tl) * 68 + d4 * 4];
            raw0 += z0.x * g.x + z0.y * g.y + z0.z * g.z + z0.w * g.w;
            raw1 += z1.x * g.x + z1.y * g.y + z1.z * g.z + z1.w * g.w;
            raw2 += z2.x * g.x + z2.y * g.y + z2.z * g.z + z2.w * g.w;
            raw3 += z3.x * g.x + z3.y * g.y + z3.z * g.z + z3.w * g.w;
        }
        __syncthreads();

        // ---- rescale accumulators; softmax over K; store w = p_k * e_t ----
        const float fac = sm_fac;
        const float Mn  = sm_M;
        a0 *= fac; a1 *= fac; a2 *= fac; a3 *= fac;
        float raws[4] = {raw0, raw1, raw2, raw3};
        #pragma unroll
        for (int s = 0; s < 4; s++) {
            int row  = s * 16 + tl;
            float mz = sm_m[row], rz = sm_r[row];
            float sc = SCALEV * (rz * (raws[s] - mz * sgp_k) + ck_k);
            float mx = sc;
            #pragma unroll
            for (int m = 8; m; m >>= 1) mx = fmaxf(mx, __shfl_xor_sync(~0u, mx, m));
            float e = __expf(sc - mx);
            float ssum = e;
            #pragma unroll
            for (int m = 8; m; m >>= 1) ssum += __shfl_xor_sync(~0u, ssum, m);
            float et = __expf(st_full[tbase + row] - Mn);
            sw[row * 16 + k] = e * (et / ssum);
        }
        __syncthreads();

        // ---- aggregation: acc[k,d] += w[t,k] * z[t,d] (z from SMEM) ----
        #pragma unroll 8
        for (int t = 0; t < 64; t++) {
            float zv  = z_s[t * 68 + dd];
            float4 w4 = *(const float4*)&sw[t * 16 + kg * 4];
            a0 += w4.x * zv;
            a1 += w4.y * zv;
            a2 += w4.z * zv;
            a3 += w4.w * zv;
        }
        __syncthreads();
    }

    // ---- denominator S = sum_t exp(st - M_final) ----
    const float Mf = sm_M;
    float ls = 0.f;
    #pragma unroll
    for (int j = 0; j < 4; j++) ls += __expf(st_full[tid * 4 + j] - Mf);
    #pragma unroll
    for (int m = 16; m; m >>= 1) ls += __shfl_xor_sync(~0u, ls, m);
    if (lane == 0) sm_red[wid] = ls;
    __syncthreads();
    if (tid == 0) {
        float t = 0.f;
        #pragma unroll
        for (int i = 0; i < 8; i++) t += sm_red[i];
        sm_S = t;
    }
    __syncthreads();
    const float invS = 1.0f / sm_S;

    // ---- stage final 16x64 matrix (+ beta_seq) into z_s, then LN rows ----
    {
        float av[4] = {a0, a1, a2, a3};
        #pragma unroll
        for (int j = 0; j < 4; j++) {
            int kk = kg * 4 + j;
            z_s[kk * 68 + dd] = beta_seq[kk * 64 + dd] + av[j] * invS;
        }
    }
    __syncthreads();

    const float* g4 = gamma + 4 * 64;
    const float* b4 = beta  + 4 * 64;
    #pragma unroll
    for (int rr = 0; rr < 2; rr++) {
        int row = wid * 2 + rr;
        float v1 = z_s[row * 68 + lane];
        float v2 = z_s[row * 68 + lane + 32];
        float s = v1 + v2, sq = v1 * v1 + v2 * v2;
        #pragma unroll
        for (int m = 16; m; m >>= 1) {
            s  += __shfl_xor_sync(~0u, s,  m);
            sq += __shfl_xor_sync(~0u, sq, m);
        }
        float mean = s * (1.f / 64.f);
        float var  = sq * (1.f / 64.f) - mean * mean;
        float r    = rsqrtf(var + EPSV);
        size_t ob = ((size_t)b * 16 + row) * 64;
        out[ob + lane]      = (v1 - mean) * r * g4[lane]      + b4[lane];
        out[ob + lane + 32] = (v2 - mean) * r * g4[lane + 32] + b4[lane + 32];
    }
}

// ---------------------------------------------------------------------------
// Launch. Input order (metadata): z, prototypes, alphas, b_bias, W, Wb,
// ln_gamma, ln_beta, beta_seq. Output: [B,16,64] f32.
// ---------------------------------------------------------------------------
extern "C" void kernel_launch(void* const* d_in, const int* in_sizes, int n_in,
                              void* d_out, int out_size)
{
    const float* z        = (const float*)d_in[0];
    const float* prot     = (const float*)d_in[1];
    const float* alphas   = (const float*)d_in[2];
    const float* b_bias   = (const float*)d_in[3];
    const float* W        = (const float*)d_in[4];
    // d_in[5] = Wb: only enters scores as a per-batch constant -> softmax-invariant, unused.
    const float* gamma    = (const float*)d_in[6];
    const float* beta     = (const float*)d_in[7];
    const float* beta_seq = (const float*)d_in[8];
    float* out = (float*)d_out;

    const int T = in_sizes[2] / 64;                 // 1024
    const int B = in_sizes[0] / (T * 64);           // 512

    setup_kernel<<<1, 512>>>(prot, gamma, beta);
    dse_main_kernel<<<B, 256>>>(z, alphas, b_bias, W, gamma, beta, beta_seq, out);
}

// round 10
// speedup vs baseline: 1.1263x; 1.1263x over previous
#include <cuda_runtime.h>
#include <math.h>
#include <float.h>
#include <stdint.h>

#define EPSV 1e-6f
#define SCALEV 0.125f

typedef unsigned long long u64;

__device__ __forceinline__ u64 fma2(u64 a, u64 b, u64 c){ u64 d; asm("fma.rn.f32x2 %0,%1,%2,%3;":"=l"(d):"l"(a),"l"(b),"l"(c)); return d; }
__device__ __forceinline__ u64 add2(u64 a, u64 b){ u64 d; asm("add.rn.f32x2 %0,%1,%2;":"=l"(d):"l"(a),"l"(b)); return d; }
__device__ __forceinline__ u64 mul2(u64 a, u64 b){ u64 d; asm("mul.rn.f32x2 %0,%1,%2;":"=l"(d):"l"(a),"l"(b)); return d; }
__device__ __forceinline__ u64 pack2(float x, float y){ u64 d; asm("mov.b64 %0,{%1,%2};":"=l"(d):"f"(x),"f"(y)); return d; }
__device__ __forceinline__ float hadd2(u64 a){ float x,y; asm("mov.b64 {%0,%1},%2;":"=f"(x),"=f"(y):"l"(a)); return x+y; }
__device__ __forceinline__ void cp16(uint32_t dst, const void* src){
    asm volatile("cp.async.cg.shared.global [%0], [%1], 16;" :: "r"(dst), "l"(src));
}

__device__ float d_gp[16 * 64];
__device__ float d_sgp[16];
__device__ float d_ck[16];

__global__ void setup_kernel(const float* __restrict__ prot,
                             const float* __restrict__ gamma,
                             const float* __restrict__ beta)
{
    int w = threadIdx.x >> 5;
    int l = threadIdx.x & 31;
    if (w >= 16) return;
    const float* g0 = gamma;       const float* b0 = beta;
    const float* g1 = gamma + 64;  const float* b1 = beta + 64;

    float p0 = prot[w * 64 + l];
    float p1 = prot[w * 64 + l + 32];
    float s = p0 + p1, q = p0 * p0 + p1 * p1;
    #pragma unroll
    for (int m = 16; m; m >>= 1) {
        s += __shfl_xor_sync(~0u, s, m);
        q += __shfl_xor_sync(~0u, q, m);
    }
    float mean = s * (1.f / 64.f);
    float var  = q * (1.f / 64.f) - mean * mean;
    float r    = rsqrtf(var + EPSV);
    float pn0 = (p0 - mean) * r * g1[l]      + b1[l];
    float pn1 = (p1 - mean) * r * g1[l + 32] + b1[l + 32];
    float gp0 = g0[l] * pn0;
    float gp1 = g0[l + 32] * pn1;
    d_gp[w * 64 + l]      = gp0;
    d_gp[w * 64 + l + 32] = gp1;
    float sg  = gp0 + gp1;
    float ckp = b0[l] * pn0 + b0[l + 32] * pn1;
    #pragma unroll
    for (int m = 16; m; m >>= 1) {
        sg  += __shfl_xor_sync(~0u, sg, m);
        ckp += __shfl_xor_sync(~0u, ckp, m);
    }
    if (l == 0) { d_sgp[w] = sg; d_ck[w] = ckp; }
}

__global__ __launch_bounds__(256, 3)
void dse_main_kernel(const float* __restrict__ z,
                     const float* __restrict__ alphas,
                     const float* __restrict__ b_bias,
                     const float* __restrict__ W,
                     const float* __restrict__ gamma,
                     const float* __restrict__ beta,
                     const float* __restrict__ beta_seq,
                     float* __restrict__ out)
{
    __shared__ __align__(16) float z_s[2][64 * 68];   // double-buffered tile
    __shared__ __align__(16) float2 sw2[64 * 16];     // (w,w) duplicated weights
    __shared__ __align__(16) float gp_s[16 * 68];
    __shared__ __align__(16) float sm_u[64];
    __shared__ __align__(16) float sm_m[64];
    __shared__ __align__(16) float sm_r[64];
    __shared__ __align__(16) float st_s[64];
    __shared__ __align__(16) float sm_q[64];
    __shared__ float sm_sgp[16], sm_ck[16];
    __shared__ float sm_su;

    const int tid  = threadIdx.x;
    const int lane = tid & 31;
    const int wid  = tid >> 5;
    const int b    = blockIdx.x;
    const size_t zb = (size_t)b * (1024 * 64);

    const int srow = tid >> 2;
    const int sc0  = (tid & 3) * 16;

    const uint32_t zshA = (uint32_t)__cvta_generic_to_shared(&z_s[0][srow * 68 + sc0]);
    const uint32_t zshB = (uint32_t)__cvta_generic_to_shared(&z_s[1][srow * 68 + sc0]);
    const float* gsrc = z + zb + (size_t)srow * 64 + sc0;
    const float* asrc = alphas + (size_t)srow * 64 + sc0;

    // tile 0 fetch
    #pragma unroll
    for (int j = 0; j < 4; j++) cp16(zshA + j * 16, gsrc + 4 * j);
    asm volatile("cp.async.commit_group;" ::: "memory");

    // ---- prologue ----
    if (wid == 0) {
        const float* g3 = gamma + 3 * 64;
        const float* b3 = beta  + 3 * 64;
        const float* g2 = gamma + 2 * 64;
        const int d1 = lane, d2 = lane + 32;
        float x1 = alphas[1023 * 64 + d1] + z[zb + 1023 * 64 + d1] + b_bias[d1];
        float x2 = alphas[1023 * 64 + d2] + z[zb + 1023 * 64 + d2] + b_bias[d2];
        float s = x1 + x2, sq = x1 * x1 + x2 * x2;
        #pragma unroll
        for (int m = 16; m; m >>= 1) {
            s  += __shfl_xor_sync(~0u, s,  m);
            sq += __shfl_xor_sync(~0u, sq, m);
        }
        float mean = s * (1.f / 64.f);
        float var  = sq * (1.f / 64.f) - mean * mean;
        float r    = rsqrtf(var + EPSV);
        float q1 = (x1 - mean) * r * g3[d1] + b3[d1];
        float q2 = (x2 - mean) * r * g3[d2] + b3[d2];
        sm_q[d1] = q1; sm_q[d2] = q2;
        __syncwarp();
        float wq1 = 0.f, wq2 = 0.f;
        #pragma unroll 4
        for (int e4 = 0; e4 < 16; e4++) {
            float4 qv = *(const float4*)&sm_q[e4 * 4];
            float4 w1 = *(const float4*)(W + d1 * 64 + e4 * 4);
            float4 w2 = *(const float4*)(W + d2 * 64 + e4 * 4);
            wq1 += w1.x * qv.x + w1.y * qv.y + w1.z * qv.z + w1.w * qv.w;
            wq2 += w2.x * qv.x + w2.y * qv.y + w2.z * qv.z + w2.w * qv.w;
        }
        float u1 = g2[d1] * (q1 + wq1);
        float u2 = g2[d2] * (q2 + wq2);
        sm_u[d1] = u1; sm_u[d2] = u2;
        float su = u1 + u2;
        #pragma unroll
        for (int m = 16; m; m >>= 1) su += __shfl_xor_sync(~0u, su, m);
        if (lane == 0) sm_su = su;
    } else {
        for (int i = tid - 32; i < 256; i += 224) {
            int row = i >> 4, c4 = (i & 15) * 4;
            *(float4*)&gp_s[row * 68 + c4] = *(const float4*)&d_gp[row * 64 + c4];
        }
        if (tid >= 32 && tid < 48) sm_sgp[tid - 32] = d_sgp[tid - 32];
        if (tid >= 48 && tid < 64) sm_ck[tid - 48]  = d_ck[tid - 48];
    }
    __syncthreads();

    const float su = sm_su;
    // GEMM mapping
    const int k  = tid & 15;
    const int tl = tid >> 4;
    const float sgp_k = sm_sgp[k];
    const float ck_k  = sm_ck[k];
    // aggregation mapping
    const int idx  = tid & 63;
    const int dg4  = (idx & 15) * 4;
    const int kg4  = (idx >> 4) * 4;
    const int tcb  = (tid >> 6) * 16;

    u64 acc[4][2] = {{0,0},{0,0},{0,0},{0,0}};   // [kk][d-pair]
    float Mold = -FLT_MAX, S_run = 0.f;

    #pragma unroll 1
    for (int tile = 0; tile < 16; tile++) {
        const int buf = tile & 1;
        const float* zc = z_s[buf];

        // alphas loads (global, issued before the cp wait)
        const float* ar = asrc + (size_t)tile * 4096;
        ulonglong2 aw0 = *(const ulonglong2*)(ar);
        ulonglong2 aw1 = *(const ulonglong2*)(ar + 4);
        ulonglong2 aw2 = *(const ulonglong2*)(ar + 8);
        ulonglong2 aw3 = *(const ulonglong2*)(ar + 12);

        asm volatile("cp.async.wait_group 0;" ::: "memory");
        __syncthreads();   // z_s[buf] fully staged for all threads

        // ---- stats + scoreT logit ----
        {
            const float* zr = &zc[srow * 68 + sc0];
            ulonglong2 aws[4] = {aw0, aw1, aw2, aw3};
            u64 zs2 = 0, zq2 = 0, xs2 = 0, xq2 = 0, xu2 = 0;
            #pragma unroll
            for (int j = 0; j < 4; j++) {
                ulonglong2 zw = *(const ulonglong2*)(zr + 4 * j);
                ulonglong2 uw = *(const ulonglong2*)(&sm_u[sc0 + 4 * j]);
                zs2 = add2(zs2, zw.x); zq2 = fma2(zw.x, zw.x, zq2);
                u64 xa = add2(zw.x, aws[j].x);
                xs2 = add2(xs2, xa); xq2 = fma2(xa, xa, xq2); xu2 = fma2(xa, uw.x, xu2);
                zs2 = add2(zs2, zw.y); zq2 = fma2(zw.y, zw.y, zq2);
                u64 xb = add2(zw.y, aws[j].y);
                xs2 = add2(xs2, xb); xq2 = fma2(xb, xb, xq2); xu2 = fma2(xb, uw.y, xu2);
            }
            float zs = hadd2(zs2), zq = hadd2(zq2);
            float xs = hadd2(xs2), xq = hadd2(xq2), xu = hadd2(xu2);
            #pragma unroll
            for (int m = 1; m < 4; m <<= 1) {
                zs += __shfl_xor_sync(~0u, zs, m);
                zq += __shfl_xor_sync(~0u, zq, m);
                xs += __shfl_xor_sync(~0u, xs, m);
                xq += __shfl_xor_sync(~0u, xq, m);
                xu += __shfl_xor_sync(~0u, xu, m);
            }
            if ((tid & 3) == 0) {
                float mz = zs * (1.f / 64.f);
                float vz = zq * (1.f / 64.f) - mz * mz;
                sm_m[srow] = mz;
                sm_r[srow] = rsqrtf(vz + EPSV);
                float mx = xs * (1.f / 64.f);
                float vx = xq * (1.f / 64.f) - mx * mx;
                st_s[srow] = SCALEV * (rsqrtf(vx + EPSV) * (xu - mx * su));
            }
        }
        __syncthreads();   // bar1

        // prefetch next tile into other buffer
        if (tile < 15) {
            const float* s2 = gsrc + (size_t)(tile + 1) * 4096;
            uint32_t dsh = buf ? zshA : zshB;
            #pragma unroll
            for (int j = 0; j < 4; j++) cp16(dsh + j * 16, s2 + 4 * j);
            asm volatile("cp.async.commit_group;" ::: "memory");
        }

        // ---- online softmax-T update (redundant in every thread) ----
        float Mn;
        {
            float sa = st_s[lane], sb = st_s[lane + 32];
            float v = fmaxf(sa, sb);
            #pragma unroll
            for (int m = 16; m; m >>= 1) v = fmaxf(v, __shfl_xor_sync(~0u, v, m));
            Mn = fmaxf(Mold, v);
            float facv = __expf(Mold - Mn);
            float es = __expf(sa - Mn) + __expf(sb - Mn);
            #pragma unroll
            for (int m = 16; m; m >>= 1) es += __shfl_xor_sync(~0u, es, m);
            S_run = S_run * facv + es;
            Mold = Mn;
            u64 f2 = pack2(facv, facv);
            #pragma unroll
            for (int kk = 0; kk < 4; kk++) {
                acc[kk][0] = mul2(acc[kk][0], f2);
                acc[kk][1] = mul2(acc[kk][1], f2);
            }
        }

        // ---- scoresK GEMM: 4 rows per thread, packed over d ----
        u64 aa0 = 0, aa1 = 0, aa2 = 0, aa3 = 0;
        #pragma unroll
        for (int d4 = 0; d4 < 16; d4++) {
            ulonglong2 g  = *(const ulonglong2*)&gp_s[k * 68 + d4 * 4];
            ulonglong2 z0 = *(const ulonglong2*)&zc[tl * 68 + d4 * 4];
            ulonglong2 z1 = *(const ulonglong2*)&zc[(tl + 16) * 68 + d4 * 4];
            ulonglong2 z2 = *(const ulonglong2*)&zc[(tl + 32) * 68 + d4 * 4];
            ulonglong2 z3 = *(const ulonglong2*)&zc[(tl + 48) * 68 + d4 * 4];
            aa0 = fma2(z0.x, g.x, aa0); aa0 = fma2(z0.y, g.y, aa0);
            aa1 = fma2(z1.x, g.x, aa1); aa1 = fma2(z1.y, g.y, aa1);
            aa2 = fma2(z2.x, g.x, aa2); aa2 = fma2(z2.y, g.y, aa2);
            aa3 = fma2(z3.x, g.x, aa3); aa3 = fma2(z3.y, g.y, aa3);
        }
        float raws[4] = {hadd2(aa0), hadd2(aa1), hadd2(aa2), hadd2(aa3)};

        // ---- softmax over K; store duplicated weights ----
        #pragma unroll
        for (int s = 0; s < 4; s++) {
            int row  = s * 16 + tl;
            float sc = SCALEV * (sm_r[row] * (raws[s] - sm_m[row] * sgp_k) + ck_k);
            float mx = sc;
            #pragma unroll
            for (int m = 8; m; m >>= 1) mx = fmaxf(mx, __shfl_xor_sync(~0u, mx, m));
            float e = __expf(sc - mx);
            float ssum = e;
            #pragma unroll
            for (int m = 8; m; m >>= 1) ssum += __shfl_xor_sync(~0u, ssum, m);
            float et = __expf(st_s[row] - Mn);
            float wv = e * (et / ssum);
            sw2[row * 16 + k] = make_float2(wv, wv);
        }
        __syncthreads();   // bar2

        // ---- aggregation: 16 tokens, 4 k's x 4 d's, packed ----
        #pragma unroll
        for (int t0 = 0; t0 < 16; t0++) {
            int t = tcb + t0;
            ulonglong2 zp = *(const ulonglong2*)&zc[t * 68 + dg4];
            ulonglong2 w01 = *(const ulonglong2*)&sw2[t * 16 + kg4];
            ulonglong2 w23 = *(const ulonglong2*)&sw2[t * 16 + kg4 + 2];
            acc[0][0] = fma2(zp.x, w01.x, acc[0][0]); acc[0][1] = fma2(zp.y, w01.x, acc[0][1]);
            acc[1][0] = fma2(zp.x, w01.y, acc[1][0]); acc[1][1] = fma2(zp.y, w01.y, acc[1][1]);
            acc[2][0] = fma2(zp.x, w23.x, acc[2][0]); acc[2][1] = fma2(zp.y, w23.x, acc[2][1]);
            acc[3][0] = fma2(zp.x, w23.y, acc[3][0]); acc[3][1] = fma2(zp.y, w23.y, acc[3][1]);
        }
        __syncthreads();   // protects sw2 / st_s / sm_m for next tile
    }

    const float invS = 1.0f / S_run;

    // ---- reduce 4 t-slices: partials -> smem ----
    float* red = &z_s[0][0];   // reuse, 4 * 1024 floats
    {
        const int cb = (tid >> 6) * 1024;
        #pragma unroll
        for (int kk = 0; kk < 4; kk++) {
            float2 lo, hi;
            asm("mov.b64 {%0,%1},%2;":"=f"(lo.x),"=f"(lo.y):"l"(acc[kk][0]));
            asm("mov.b64 {%0,%1},%2;":"=f"(hi.x),"=f"(hi.y):"l"(acc[kk][1]));
            float4 v = make_float4(lo.x, lo.y, hi.x, hi.y);
            *(float4*)&red[cb + (kg4 + kk) * 64 + dg4] = v;
        }
    }
    __syncthreads();

    // ---- final sum + beta_seq + LN + store ----
    {
        const int c4 = tid * 4;            // k = tid>>4, d0 = (tid&15)*4
        const int kk = tid >> 4;
        const int d0 = (tid & 15) * 4;
        float4 v0 = *(const float4*)&red[c4];
        float4 v1 = *(const float4*)&red[1024 + c4];
        float4 v2 = *(const float4*)&red[2048 + c4];
        float4 v3 = *(const float4*)&red[3072 + c4];
        float4 bs = *(const float4*)&beta_seq[c4];
        float o0 = (v0.x + v1.x + v2.x + v3.x) * invS + bs.x;
        float o1 = (v0.y + v1.y + v2.y + v3.y) * invS + bs.y;
        float o2 = (v0.z + v1.z + v2.z + v3.z) * invS + bs.z;
        float o3 = (v0.w + v1.w + v2.w + v3.w) * invS + bs.w;
        float s  = o0 + o1 + o2 + o3;
        float sq = o0 * o0 + o1 * o1 + o2 * o2 + o3 * o3;
        #pragma unroll
        for (int m = 8; m; m >>= 1) {
            s  += __shfl_xor_sync(~0u, s,  m);
            sq += __shfl_xor_sync(~0u, sq, m);
        }
        float mean = s * (1.f / 64.f);
        float var  = sq * (1.f / 64.f) - mean * mean;
        float r    = rsqrtf(var + EPSV);
        float4 g4 = *(const float4*)&gamma[4 * 64 + d0];
        float4 b4 = *(const float4*)&beta[4 * 64 + d0];
        float4 ov;
        ov.x = (o0 - mean) * r * g4.x + b4.x;
        ov.y = (o1 - mean) * r * g4.y + b4.y;
        ov.z = (o2 - mean) * r * g4.z + b4.z;
        ov.w = (o3 - mean) * r * g4.w + b4.w;
        *(float4*)&out[((size_t)b * 16 + kk) * 64 + d0] = ov;
    }
}

extern "C" void kernel_launch(void* const* d_in, const int* in_sizes, int n_in,
                              void* d_out, int out_size)
{
    const float* z        = (const float*)d_in[0];
    const float* prot     = (const float*)d_in[1];
    const float* alphas   = (const float*)d_in[2];
    const float* b_bias   = (const float*)d_in[3];
    const float* W        = (const float*)d_in[4];
    // d_in[5] = Wb: softmax-invariant constant, unused.
    const float* gamma    = (const float*)d_in[6];
    const float* beta     = (const float*)d_in[7];
    const float* beta_seq = (const float*)d_in[8];
    float* out = (float*)d_out;

    const int T = in_sizes[2] / 64;
    const int B = in_sizes[0] / (T * 64);

    setup_kernel<<<1, 512>>>(prot, gamma, beta);
    dse_main_kernel<<<B, 256>>>(z, alphas, b_bias, W, gamma, beta, beta_seq, out);
}

// round 11
// speedup vs baseline: 1.2410x; 1.1018x over previous
#include <cuda_runtime.h>
#include <math.h>
#include <float.h>
#include <stdint.h>

#define EPSV 1e-6f
#define SCALEV 0.125f

typedef unsigned long long u64;

__device__ __forceinline__ u64 fma2(u64 a, u64 b, u64 c){ u64 d; asm("fma.rn.f32x2 %0,%1,%2,%3;":"=l"(d):"l"(a),"l"(b),"l"(c)); return d; }
__device__ __forceinline__ u64 add2(u64 a, u64 b){ u64 d; asm("add.rn.f32x2 %0,%1,%2;":"=l"(d):"l"(a),"l"(b)); return d; }
__device__ __forceinline__ u64 mul2(u64 a, u64 b){ u64 d; asm("mul.rn.f32x2 %0,%1,%2;":"=l"(d):"l"(a),"l"(b)); return d; }
__device__ __forceinline__ u64 pack2(float x, float y){ u64 d; asm("mov.b64 %0,{%1,%2};":"=l"(d):"f"(x),"f"(y)); return d; }
__device__ __forceinline__ float hadd2(u64 a){ float x,y; asm("mov.b64 {%0,%1},%2;":"=f"(x),"=f"(y):"l"(a)); return x+y; }
__device__ __forceinline__ void cp16(uint32_t dst, const void* src){
    asm volatile("cp.async.cg.shared.global [%0], [%1], 16;" :: "r"(dst), "l"(src));
}

__device__ float d_gp[16 * 64];
__device__ float d_sgp[16];
__device__ float d_ck[16];

__global__ void setup_kernel(const float* __restrict__ prot,
                             const float* __restrict__ gamma,
                             const float* __restrict__ beta)
{
    int w = threadIdx.x >> 5;
    int l = threadIdx.x & 31;
    if (w >= 16) return;
    const float* g0 = gamma;       const float* b0 = beta;
    const float* g1 = gamma + 64;  const float* b1 = beta + 64;

    float p0 = prot[w * 64 + l];
    float p1 = prot[w * 64 + l + 32];
    float s = p0 + p1, q = p0 * p0 + p1 * p1;
    #pragma unroll
    for (int m = 16; m; m >>= 1) {
        s += __shfl_xor_sync(~0u, s, m);
        q += __shfl_xor_sync(~0u, q, m);
    }
    float mean = s * (1.f / 64.f);
    float var  = q * (1.f / 64.f) - mean * mean;
    float r    = rsqrtf(var + EPSV);
    float pn0 = (p0 - mean) * r * g1[l]      + b1[l];
    float pn1 = (p1 - mean) * r * g1[l + 32] + b1[l + 32];
    float gp0 = g0[l] * pn0;
    float gp1 = g0[l + 32] * pn1;
    d_gp[w * 64 + l]      = gp0;
    d_gp[w * 64 + l + 32] = gp1;
    float sg  = gp0 + gp1;
    float ckp = b0[l] * pn0 + b0[l + 32] * pn1;
    #pragma unroll
    for (int m = 16; m; m >>= 1) {
        sg  += __shfl_xor_sync(~0u, sg, m);
        ckp += __shfl_xor_sync(~0u, ckp, m);
    }
    if (l == 0) { d_sgp[w] = sg; d_ck[w] = ckp; }
}

// Per-tile row stats live in the z-tile padding columns:
//   z_s[buf][row*68 + 64] = mean(z_row)
//   z_s[buf][row*68 + 65] = rsqrt(var(z_row)+eps)
//   z_s[buf][row*68 + 66] = scoreT logit
__global__ __launch_bounds__(256, 4)
void dse_main_kernel(const float* __restrict__ z,
                     const float* __restrict__ alphas,
                     const float* __restrict__ b_bias,
                     const float* __restrict__ W,
                     const float* __restrict__ gamma,
                     const float* __restrict__ beta,
                     const float* __restrict__ beta_seq,
                     float* __restrict__ out)
{
    __shared__ __align__(16) float z_s[2][64 * 68];   // 34816 B
    __shared__ __align__(16) float sw[2][64 * 16];    //  8192 B
    __shared__ __align__(16) float gp_s[16 * 68];     //  4352 B
    __shared__ __align__(16) float sm_u[64];
    __shared__ __align__(16) float sm_q[64];
    __shared__ float sm_su;

    const int tid  = threadIdx.x;
    const int lane = tid & 31;
    const int wid  = tid >> 5;
    const int b    = blockIdx.x;
    const size_t zb = (size_t)b * (1024 * 64);

    const int srow = tid >> 2;
    const int sc0  = (tid & 3) * 16;

    const uint32_t zshA = (uint32_t)__cvta_generic_to_shared(&z_s[0][srow * 68 + sc0]);
    const uint32_t zshB = (uint32_t)__cvta_generic_to_shared(&z_s[1][srow * 68 + sc0]);
    const float* gsrc = z + zb + (size_t)srow * 64 + sc0;
    const float* asrc = alphas + (size_t)srow * 64 + sc0;

    // tile 0 fetch
    #pragma unroll
    for (int j = 0; j < 4; j++) cp16(zshA + j * 16, gsrc + 4 * j);
    asm volatile("cp.async.commit_group;" ::: "memory");

    // ---- prologue ----
    if (wid == 0) {
        const float* g3 = gamma + 3 * 64;
        const float* b3 = beta  + 3 * 64;
        const float* g2 = gamma + 2 * 64;
        const int d1 = lane, d2 = lane + 32;
        float x1 = alphas[1023 * 64 + d1] + z[zb + 1023 * 64 + d1] + b_bias[d1];
        float x2 = alphas[1023 * 64 + d2] + z[zb + 1023 * 64 + d2] + b_bias[d2];
        float s = x1 + x2, sq = x1 * x1 + x2 * x2;
        #pragma unroll
        for (int m = 16; m; m >>= 1) {
            s  += __shfl_xor_sync(~0u, s,  m);
            sq += __shfl_xor_sync(~0u, sq, m);
        }
        float mean = s * (1.f / 64.f);
        float var  = sq * (1.f / 64.f) - mean * mean;
        float r    = rsqrtf(var + EPSV);
        float q1 = (x1 - mean) * r * g3[d1] + b3[d1];
        float q2 = (x2 - mean) * r * g3[d2] + b3[d2];
        sm_q[d1] = q1; sm_q[d2] = q2;
        __syncwarp();
        float wq1 = 0.f, wq2 = 0.f;
        #pragma unroll 4
        for (int e4 = 0; e4 < 16; e4++) {
            float4 qv = *(const float4*)&sm_q[e4 * 4];
            float4 w1 = *(const float4*)(W + d1 * 64 + e4 * 4);
            float4 w2 = *(const float4*)(W + d2 * 64 + e4 * 4);
            wq1 += w1.x * qv.x + w1.y * qv.y + w1.z * qv.z + w1.w * qv.w;
            wq2 += w2.x * qv.x + w2.y * qv.y + w2.z * qv.z + w2.w * qv.w;
        }
        float u1 = g2[d1] * (q1 + wq1);
        float u2 = g2[d2] * (q2 + wq2);
        sm_u[d1] = u1; sm_u[d2] = u2;
        float su = u1 + u2;
        #pragma unroll
        for (int m = 16; m; m >>= 1) su += __shfl_xor_sync(~0u, su, m);
        if (lane == 0) sm_su = su;
    } else {
        for (int i = tid - 32; i < 256; i += 224) {
            int row = i >> 4, c4 = (i & 15) * 4;
            *(float4*)&gp_s[row * 68 + c4] = *(const float4*)&d_gp[row * 64 + c4];
        }
    }
    __syncthreads();

    const float su = sm_su;
    // GEMM mapping
    const int k  = tid & 15;
    const int tl = tid >> 4;
    const float sgp_k = d_sgp[k];
    const float ck_k  = d_ck[k];
    // aggregation mapping
    const int idx  = tid & 63;
    const int dg4  = (idx & 15) * 4;
    const int kg4  = (idx >> 4) * 4;
    const int tcb  = (tid >> 6) * 16;

    u64 acc[4][2] = {{0,0},{0,0},{0,0},{0,0}};
    float Mold = -FLT_MAX, S_run = 0.f;

    #pragma unroll 1
    for (int tile = 0; tile < 16; tile++) {
        const int buf = tile & 1;
        float* zc = z_s[buf];
        float* swb = sw[buf];

        // alphas loads (issued before cp wait)
        const float* ar = asrc + (size_t)tile * 4096;
        ulonglong2 aw0 = *(const ulonglong2*)(ar);
        ulonglong2 aw1 = *(const ulonglong2*)(ar + 4);
        ulonglong2 aw2 = *(const ulonglong2*)(ar + 8);
        ulonglong2 aw3 = *(const ulonglong2*)(ar + 12);

        asm volatile("cp.async.wait_group 0;" ::: "memory");
        __syncthreads();   // z_s[buf] staged; also closes previous tile's agg

        // ---- stats + scoreT logit (stats into pad cols of zc) ----
        {
            const float* zr = &zc[srow * 68 + sc0];
            ulonglong2 aws[4] = {aw0, aw1, aw2, aw3};
            u64 zs2 = 0, zq2 = 0, xs2 = 0, xq2 = 0, xu2 = 0;
            #pragma unroll
            for (int j = 0; j < 4; j++) {
                ulonglong2 zw = *(const ulonglong2*)(zr + 4 * j);
                ulonglong2 uw = *(const ulonglong2*)(&sm_u[sc0 + 4 * j]);
                zs2 = add2(zs2, zw.x); zq2 = fma2(zw.x, zw.x, zq2);
                u64 xa = add2(zw.x, aws[j].x);
                xs2 = add2(xs2, xa); xq2 = fma2(xa, xa, xq2); xu2 = fma2(xa, uw.x, xu2);
                zs2 = add2(zs2, zw.y); zq2 = fma2(zw.y, zw.y, zq2);
                u64 xb = add2(zw.y, aws[j].y);
                xs2 = add2(xs2, xb); xq2 = fma2(xb, xb, xq2); xu2 = fma2(xb, uw.y, xu2);
            }
            float zs = hadd2(zs2), zq = hadd2(zq2);
            float xs = hadd2(xs2), xq = hadd2(xq2), xu = hadd2(xu2);
            #pragma unroll
            for (int m = 1; m < 4; m <<= 1) {
                zs += __shfl_xor_sync(~0u, zs, m);
                zq += __shfl_xor_sync(~0u, zq, m);
                xs += __shfl_xor_sync(~0u, xs, m);
                xq += __shfl_xor_sync(~0u, xq, m);
                xu += __shfl_xor_sync(~0u, xu, m);
            }
            if ((tid & 3) == 0) {
                float mz = zs * (1.f / 64.f);
                float vz = zq * (1.f / 64.f) - mz * mz;
                zc[srow * 68 + 64] = mz;
                zc[srow * 68 + 65] = rsqrtf(vz + EPSV);
                float mx = xs * (1.f / 64.f);
                float vx = xq * (1.f / 64.f) - mx * mx;
                zc[srow * 68 + 66] = SCALEV * (rsqrtf(vx + EPSV) * (xu - mx * su));
            }
        }
        __syncthreads();   // bar1

        // prefetch next tile into other buffer
        if (tile < 15) {
            const float* s2 = gsrc + (size_t)(tile + 1) * 4096;
            uint32_t dsh = buf ? zshA : zshB;
            #pragma unroll
            for (int j = 0; j < 4; j++) cp16(dsh + j * 16, s2 + 4 * j);
            asm volatile("cp.async.commit_group;" ::: "memory");
        }

        // ---- online softmax-T update (redundant per thread) ----
        float Mn;
        {
            float sa = zc[lane * 68 + 66], sb = zc[(lane + 32) * 68 + 66];
            float v = fmaxf(sa, sb);
            #pragma unroll
            for (int m = 16; m; m >>= 1) v = fmaxf(v, __shfl_xor_sync(~0u, v, m));
            Mn = fmaxf(Mold, v);
            float facv = __expf(Mold - Mn);
            float es = __expf(sa - Mn) + __expf(sb - Mn);
            #pragma unroll
            for (int m = 16; m; m >>= 1) es += __shfl_xor_sync(~0u, es, m);
            S_run = S_run * facv + es;
            Mold = Mn;
            u64 f2 = pack2(facv, facv);
            #pragma unroll
            for (int kk = 0; kk < 4; kk++) {
                acc[kk][0] = mul2(acc[kk][0], f2);
                acc[kk][1] = mul2(acc[kk][1], f2);
            }
        }

        // ---- scoresK GEMM ----
        u64 aa0 = 0, aa1 = 0, aa2 = 0, aa3 = 0;
        #pragma unroll
        for (int d4 = 0; d4 < 16; d4++) {
            ulonglong2 g  = *(const ulonglong2*)&gp_s[k * 68 + d4 * 4];
            ulonglong2 z0 = *(const ulonglong2*)&zc[tl * 68 + d4 * 4];
            ulonglong2 z1 = *(const ulonglong2*)&zc[(tl + 16) * 68 + d4 * 4];
            ulonglong2 z2 = *(const ulonglong2*)&zc[(tl + 32) * 68 + d4 * 4];
            ulonglong2 z3 = *(const ulonglong2*)&zc[(tl + 48) * 68 + d4 * 4];
            aa0 = fma2(z0.x, g.x, aa0); aa0 = fma2(z0.y, g.y, aa0);
            aa1 = fma2(z1.x, g.x, aa1); aa1 = fma2(z1.y, g.y, aa1);
            aa2 = fma2(z2.x, g.x, aa2); aa2 = fma2(z2.y, g.y, aa2);
            aa3 = fma2(z3.x, g.x, aa3); aa3 = fma2(z3.y, g.y, aa3);
        }
        float raws[4] = {hadd2(aa0), hadd2(aa1), hadd2(aa2), hadd2(aa3)};

        // ---- softmax over K; store weights ----
        #pragma unroll
        for (int s = 0; s < 4; s++) {
            int row  = s * 16 + tl;
            float mz = zc[row * 68 + 64];
            float rz = zc[row * 68 + 65];
            float sc = SCALEV * (rz * (raws[s] - mz * sgp_k) + ck_k);
            float mx = sc;
            #pragma unroll
            for (int m = 8; m; m >>= 1) mx = fmaxf(mx, __shfl_xor_sync(~0u, mx, m));
            float e = __expf(sc - mx);
            float ssum = e;
            #pragma unroll
            for (int m = 8; m; m >>= 1) ssum += __shfl_xor_sync(~0u, ssum, m);
            float et = __expf(zc[row * 68 + 66] - Mn);
            swb[row * 16 + k] = e * (et / ssum);
        }
        __syncthreads();   // bar2 — sw[buf] ready

        // ---- aggregation: 16 tokens, 4 k's x 4 d's ----
        #pragma unroll
        for (int t0 = 0; t0 < 16; t0++) {
            int t = tcb + t0;
            ulonglong2 zp = *(const ulonglong2*)&zc[t * 68 + dg4];
            float4 w4 = *(const float4*)&swb[t * 16 + kg4];
            u64 w0 = pack2(w4.x, w4.x), w1 = pack2(w4.y, w4.y);
            u64 w2 = pack2(w4.z, w4.z), w3 = pack2(w4.w, w4.w);
            acc[0][0] = fma2(zp.x, w0, acc[0][0]); acc[0][1] = fma2(zp.y, w0, acc[0][1]);
            acc[1][0] = fma2(zp.x, w1, acc[1][0]); acc[1][1] = fma2(zp.y, w1, acc[1][1]);
            acc[2][0] = fma2(zp.x, w2, acc[2][0]); acc[2][1] = fma2(zp.y, w2, acc[2][1]);
            acc[3][0] = fma2(zp.x, w3, acc[3][0]); acc[3][1] = fma2(zp.y, w3, acc[3][1]);
        }
        // no end barrier: next tile's wait+bar closes this phase
    }

    const float invS = 1.0f / S_run;

    __syncthreads();   // all agg done before reusing z_s[0] as scratch
    float* red = &z_s[0][0];
    {
        const int cb = (tid >> 6) * 1024;
        #pragma unroll
        for (int kk = 0; kk < 4; kk++) {
            float2 lo, hi;
            asm("mov.b64 {%0,%1},%2;":"=f"(lo.x),"=f"(lo.y):"l"(acc[kk][0]));
            asm("mov.b64 {%0,%1},%2;":"=f"(hi.x),"=f"(hi.y):"l"(acc[kk][1]));
            float4 v = make_float4(lo.x, lo.y, hi.x, hi.y);
            *(float4*)&red[cb + (kg4 + kk) * 64 + dg4] = v;
        }
    }
    __syncthreads();

    // ---- final sum + beta_seq + LN + store ----
    {
        const int c4 = tid * 4;
        const int kk = tid >> 4;
        const int d0 = (tid & 15) * 4;
        float4 v0 = *(const float4*)&red[c4];
        float4 v1 = *(const float4*)&red[1024 + c4];
        float4 v2 = *(const float4*)&red[2048 + c4];
        float4 v3 = *(const float4*)&red[3072 + c4];
        float4 bs = *(const float4*)&beta_seq[c4];
        float o0 = (v0.x + v1.x + v2.x + v3.x) * invS + bs.x;
        float o1 = (v0.y + v1.y + v2.y + v3.y) * invS + bs.y;
        float o2 = (v0.z + v1.z + v2.z + v3.z) * invS + bs.z;
        float o3 = (v0.w + v1.w + v2.w + v3.w) * invS + bs.w;
        float s  = o0 + o1 + o2 + o3;
        float sq = o0 * o0 + o1 * o1 + o2 * o2 + o3 * o3;
        #pragma unroll
        for (int m = 8; m; m >>= 1) {
            s  += __shfl_xor_sync(~0u, s,  m);
            sq += __shfl_xor_sync(~0u, sq, m);
        }
        float mean = s * (1.f / 64.f);
        float var  = sq * (1.f / 64.f) - mean * mean;
        float r    = rsqrtf(var + EPSV);
        float4 g4 = *(const float4*)&gamma[4 * 64 + d0];
        float4 b4 = *(const float4*)&beta[4 * 64 + d0];
        float4 ov;
        ov.x = (o0 - mean) * r * g4.x + b4.x;
        ov.y = (o1 - mean) * r * g4.y + b4.y;
        ov.z = (o2 - mean) * r * g4.z + b4.z;
        ov.w = (o3 - mean) * r * g4.w + b4.w;
        *(float4*)&out[((size_t)b * 16 + kk) * 64 + d0] = ov;
    }
}

extern "C" void kernel_launch(void* const* d_in, const int* in_sizes, int n_in,
                              void* d_out, int out_size)
{
    const float* z        = (const float*)d_in[0];
    const float* prot     = (const float*)d_in[1];
    const float* alphas   = (const float*)d_in[2];
    const float* b_bias   = (const float*)d_in[3];
    const float* W        = (const float*)d_in[4];
    // d_in[5] = Wb: softmax-invariant constant, unused.
    const float* gamma    = (const float*)d_in[6];
    const float* beta     = (const float*)d_in[7];
    const float* beta_seq = (const float*)d_in[8];
    float* out = (float*)d_out;

    const int T = in_sizes[2] / 64;
    const int B = in_sizes[0] / (T * 64);

    setup_kernel<<<1, 512>>>(prot, gamma, beta);
    dse_main_kernel<<<B, 256>>>(z, alphas, b_bias, W, gamma, beta, beta_seq, out);
}

// round 12
// speedup vs baseline: 1.3243x; 1.0672x over previous
#include <cuda_runtime.h>
#include <math.h>
#include <float.h>
#include <stdint.h>

#define EPSV 1e-6f
#define SCALEV 0.125f

typedef unsigned long long u64;

__device__ __forceinline__ u64 fma2(u64 a, u64 b, u64 c){ u64 d; asm("fma.rn.f32x2 %0,%1,%2,%3;":"=l"(d):"l"(a),"l"(b),"l"(c)); return d; }
__device__ __forceinline__ u64 add2(u64 a, u64 b){ u64 d; asm("add.rn.f32x2 %0,%1,%2;":"=l"(d):"l"(a),"l"(b)); return d; }
__device__ __forceinline__ u64 pack2(float x, float y){ u64 d; asm("mov.b64 %0,{%1,%2};":"=l"(d):"f"(x),"f"(y)); return d; }
__device__ __forceinline__ float hadd2(u64 a){ float x,y; asm("mov.b64 {%0,%1},%2;":"=f"(x),"=f"(y):"l"(a)); return x+y; }
__device__ __forceinline__ void cp16(uint32_t dst, const void* src){
    asm volatile("cp.async.cg.shared.global [%0], [%1], 16;" :: "r"(dst), "l"(src));
}

__device__ float d_gp[16 * 64];
__device__ float d_sgp[16];
__device__ float d_ck[16];

__global__ void setup_kernel(const float* __restrict__ prot,
                             const float* __restrict__ gamma,
                             const float* __restrict__ beta)
{
    int w = threadIdx.x >> 5;
    int l = threadIdx.x & 31;
    if (w >= 16) return;
    const float* g0 = gamma;       const float* b0 = beta;
    const float* g1 = gamma + 64;  const float* b1 = beta + 64;

    float p0 = prot[w * 64 + l];
    float p1 = prot[w * 64 + l + 32];
    float s = p0 + p1, q = p0 * p0 + p1 * p1;
    #pragma unroll
    for (int m = 16; m; m >>= 1) {
        s += __shfl_xor_sync(~0u, s, m);
        q += __shfl_xor_sync(~0u, q, m);
    }
    float mean = s * (1.f / 64.f);
    float var  = q * (1.f / 64.f) - mean * mean;
    float r    = rsqrtf(var + EPSV);
    float pn0 = (p0 - mean) * r * g1[l]      + b1[l];
    float pn1 = (p1 - mean) * r * g1[l + 32] + b1[l + 32];
    float gp0 = g0[l] * pn0;
    float gp1 = g0[l + 32] * pn1;
    d_gp[w * 64 + l]      = gp0;
    d_gp[w * 64 + l + 32] = gp1;
    float sg  = gp0 + gp1;
    float ckp = b0[l] * pn0 + b0[l + 32] * pn1;
    #pragma unroll
    for (int m = 16; m; m >>= 1) {
        sg  += __shfl_xor_sync(~0u, sg, m);
        ckp += __shfl_xor_sync(~0u, ckp, m);
    }
    if (l == 0) { d_sgp[w] = sg; d_ck[w] = ckp; }
}

// Per-tile row stats packed as float4 in the z-tile padding columns:
//   z_s[buf][row*68 + 64..67] = { mean(z_row), rsqrt(var+eps), exp-logit st, 0 }
__global__ __launch_bounds__(256, 4)
void dse_main_kernel(const float* __restrict__ z,
                     const float* __restrict__ alphas,
                     const float* __restrict__ b_bias,
                     const float* __restrict__ W,
                     const float* __restrict__ gamma,
                     const float* __restrict__ beta,
                     const float* __restrict__ beta_seq,
                     float* __restrict__ out)
{
    __shared__ __align__(16) float z_s[2][64 * 68];   // 34816 B
    __shared__ __align__(16) float sw[2][64 * 16];    //  8192 B
    __shared__ __align__(16) float gp_s[16 * 68];     //  4352 B
    __shared__ __align__(16) float sm_u[64];
    __shared__ __align__(16) float sm_q[64];
    __shared__ float sm_su, sm_S;

    const int tid  = threadIdx.x;
    const int lane = tid & 31;
    const int wid  = tid >> 5;
    const int b    = blockIdx.x;
    const size_t zb = (size_t)b * (1024 * 64);

    const int srow = tid >> 2;
    const int sc0  = (tid & 3) * 16;

    const uint32_t zshA = (uint32_t)__cvta_generic_to_shared(&z_s[0][srow * 68 + sc0]);
    const uint32_t zshB = (uint32_t)__cvta_generic_to_shared(&z_s[1][srow * 68 + sc0]);
    const float* gsrc = z + zb + (size_t)srow * 64 + sc0;
    const float* asrc = alphas + (size_t)srow * 64 + sc0;

    // tile 0 fetch
    #pragma unroll
    for (int j = 0; j < 4; j++) cp16(zshA + j * 16, gsrc + 4 * j);
    asm volatile("cp.async.commit_group;" ::: "memory");

    // ---- prologue ----
    if (wid == 0) {
        const float* g3 = gamma + 3 * 64;
        const float* b3 = beta  + 3 * 64;
        const float* g2 = gamma + 2 * 64;
        const int d1 = lane, d2 = lane + 32;
        float x1 = alphas[1023 * 64 + d1] + z[zb + 1023 * 64 + d1] + b_bias[d1];
        float x2 = alphas[1023 * 64 + d2] + z[zb + 1023 * 64 + d2] + b_bias[d2];
        float s = x1 + x2, sq = x1 * x1 + x2 * x2;
        #pragma unroll
        for (int m = 16; m; m >>= 1) {
            s  += __shfl_xor_sync(~0u, s,  m);
            sq += __shfl_xor_sync(~0u, sq, m);
        }
        float mean = s * (1.f / 64.f);
        float var  = sq * (1.f / 64.f) - mean * mean;
        float r    = rsqrtf(var + EPSV);
        float q1 = (x1 - mean) * r * g3[d1] + b3[d1];
        float q2 = (x2 - mean) * r * g3[d2] + b3[d2];
        sm_q[d1] = q1; sm_q[d2] = q2;
        __syncwarp();
        float wq1 = 0.f, wq2 = 0.f;
        #pragma unroll 4
        for (int e4 = 0; e4 < 16; e4++) {
            float4 qv = *(const float4*)&sm_q[e4 * 4];
            float4 w1 = *(const float4*)(W + d1 * 64 + e4 * 4);
            float4 w2 = *(const float4*)(W + d2 * 64 + e4 * 4);
            wq1 += w1.x * qv.x + w1.y * qv.y + w1.z * qv.z + w1.w * qv.w;
            wq2 += w2.x * qv.x + w2.y * qv.y + w2.z * qv.z + w2.w * qv.w;
        }
        float u1 = g2[d1] * (q1 + wq1);
        float u2 = g2[d2] * (q2 + wq2);
        sm_u[d1] = u1; sm_u[d2] = u2;
        float su = u1 + u2;
        #pragma unroll
        for (int m = 16; m; m >>= 1) su += __shfl_xor_sync(~0u, su, m);
        if (lane == 0) sm_su = su;
    } else {
        for (int i = tid - 32; i < 256; i += 224) {
            int row = i >> 4, c4 = (i & 15) * 4;
            *(float4*)&gp_s[row * 68 + c4] = *(const float4*)&d_gp[row * 64 + c4];
        }
        if (tid == 32) sm_S = 0.f;
    }
    __syncthreads();

    const float su = sm_su;
    // GEMM / softmaxK mapping
    const int k  = tid & 15;
    const int tl = tid >> 4;
    const float sgp_k = d_sgp[k];
    const float ck_k  = d_ck[k];
    // aggregation mapping
    const int idx  = tid & 63;
    const int dg4  = (idx & 15) * 4;
    const int kg4  = (idx >> 4) * 4;
    const int tcb  = (tid >> 6) * 16;

    u64 acc[4][2] = {{0,0},{0,0},{0,0},{0,0}};
    float S_part = 0.f;

    #pragma unroll 1
    for (int tile = 0; tile < 16; tile++) {
        const int buf = tile & 1;
        float* zc = z_s[buf];
        float* swb = sw[buf];

        // alphas loads (issued before cp wait)
        const float* ar = asrc + (size_t)tile * 4096;
        ulonglong2 aw0 = *(const ulonglong2*)(ar);
        ulonglong2 aw1 = *(const ulonglong2*)(ar + 4);
        ulonglong2 aw2 = *(const ulonglong2*)(ar + 8);
        ulonglong2 aw3 = *(const ulonglong2*)(ar + 12);

        asm volatile("cp.async.wait_group 0;" ::: "memory");
        __syncthreads();   // barA: z_s[buf] staged; prev tile's agg closed

        // prefetch next tile into the other buffer (no deps on this tile)
        if (tile < 15) {
            const float* s2 = gsrc + (size_t)(tile + 1) * 4096;
            uint32_t dsh = buf ? zshA : zshB;
            #pragma unroll
            for (int j = 0; j < 4; j++) cp16(dsh + j * 16, s2 + 4 * j);
            asm volatile("cp.async.commit_group;" ::: "memory");
        }

        // ---- stats + scoreT exp-logit (leaders write float4 to pad cols) ----
        {
            const float* zr = &zc[srow * 68 + sc0];
            ulonglong2 aws[4] = {aw0, aw1, aw2, aw3};
            u64 zs2 = 0, zq2 = 0, xs2 = 0, xq2 = 0, xu2 = 0;
            #pragma unroll
            for (int j = 0; j < 4; j++) {
                ulonglong2 zw = *(const ulonglong2*)(zr + 4 * j);
                ulonglong2 uw = *(const ulonglong2*)(&sm_u[sc0 + 4 * j]);
                zs2 = add2(zs2, zw.x); zq2 = fma2(zw.x, zw.x, zq2);
                u64 xa = add2(zw.x, aws[j].x);
                xs2 = add2(xs2, xa); xq2 = fma2(xa, xa, xq2); xu2 = fma2(xa, uw.x, xu2);
                zs2 = add2(zs2, zw.y); zq2 = fma2(zw.y, zw.y, zq2);
                u64 xb = add2(zw.y, aws[j].y);
                xs2 = add2(xs2, xb); xq2 = fma2(xb, xb, xq2); xu2 = fma2(xb, uw.y, xu2);
            }
            float zs = hadd2(zs2), zq = hadd2(zq2);
            float xs = hadd2(xs2), xq = hadd2(xq2), xu = hadd2(xu2);
            #pragma unroll
            for (int m = 1; m < 4; m <<= 1) {
                zs += __shfl_xor_sync(~0u, zs, m);
                zq += __shfl_xor_sync(~0u, zq, m);
                xs += __shfl_xor_sync(~0u, xs, m);
                xq += __shfl_xor_sync(~0u, xq, m);
                xu += __shfl_xor_sync(~0u, xu, m);
            }
            if ((tid & 3) == 0) {
                float mz = zs * (1.f / 64.f);
                float vz = zq * (1.f / 64.f) - mz * mz;
                float rz = rsqrtf(vz + EPSV);
                float mx = xs * (1.f / 64.f);
                float vx = xq * (1.f / 64.f) - mx * mx;
                float st = SCALEV * (rsqrtf(vx + EPSV) * (xu - mx * su));
                // |st| <~ 16 (LN-bounded), exp safe in fp32 without max-sub
                *(float4*)&zc[srow * 68 + 64] = make_float4(mz, rz, __expf(st), 0.f);
            }
        }

        // ---- scoresK GEMM (same phase: FMAs hide the stats shuffle chain) ----
        u64 aa0 = 0, aa1 = 0, aa2 = 0, aa3 = 0;
        #pragma unroll
        for (int d4 = 0; d4 < 16; d4++) {
            ulonglong2 g  = *(const ulonglong2*)&gp_s[k * 68 + d4 * 4];
            ulonglong2 z0 = *(const ulonglong2*)&zc[tl * 68 + d4 * 4];
            ulonglong2 z1 = *(const ulonglong2*)&zc[(tl + 16) * 68 + d4 * 4];
            ulonglong2 z2 = *(const ulonglong2*)&zc[(tl + 32) * 68 + d4 * 4];
            ulonglong2 z3 = *(const ulonglong2*)&zc[(tl + 48) * 68 + d4 * 4];
            aa0 = fma2(z0.x, g.x, aa0); aa0 = fma2(z0.y, g.y, aa0);
            aa1 = fma2(z1.x, g.x, aa1); aa1 = fma2(z1.y, g.y, aa1);
            aa2 = fma2(z2.x, g.x, aa2); aa2 = fma2(z2.y, g.y, aa2);
            aa3 = fma2(z3.x, g.x, aa3); aa3 = fma2(z3.y, g.y, aa3);
        }
        float raws[4] = {hadd2(aa0), hadd2(aa1), hadd2(aa2), hadd2(aa3)};
        __syncthreads();   // barB: pad-col stats visible

        // ---- softmax over K; weights w = p_k * exp(st) ----
        #pragma unroll
        for (int s = 0; s < 4; s++) {
            int row  = s * 16 + tl;
            float4 stt = *(const float4*)&zc[row * 68 + 64];   // mz, rz, et
            float sc = SCALEV * (stt.y * (raws[s] - stt.x * sgp_k) + ck_k);
            float mx = sc;
            #pragma unroll
            for (int m = 8; m; m >>= 1) mx = fmaxf(mx, __shfl_xor_sync(~0u, mx, m));
            float e = __expf(sc - mx);
            float ssum = e;
            #pragma unroll
            for (int m = 8; m; m >>= 1) ssum += __shfl_xor_sync(~0u, ssum, m);
            if (k == 0) S_part += stt.z;
            swb[row * 16 + k] = e * (stt.z / ssum);
        }
        __syncthreads();   // barC: sw[buf] ready

        // ---- aggregation: 16 tokens, 4 k's x 4 d's ----
        #pragma unroll
        for (int t0 = 0; t0 < 16; t0++) {
            int t = tcb + t0;
            ulonglong2 zp = *(const ulonglong2*)&zc[t * 68 + dg4];
            float4 w4 = *(const float4*)&swb[t * 16 + kg4];
            u64 w0 = pack2(w4.x, w4.x), w1 = pack2(w4.y, w4.y);
            u64 w2 = pack2(w4.z, w4.z), w3 = pack2(w4.w, w4.w);
            acc[0][0] = fma2(zp.x, w0, acc[0][0]); acc[0][1] = fma2(zp.y, w0, acc[0][1]);
            acc[1][0] = fma2(zp.x, w1, acc[1][0]); acc[1][1] = fma2(zp.y, w1, acc[1][1]);
            acc[2][0] = fma2(zp.x, w2, acc[2][0]); acc[2][1] = fma2(zp.y, w2, acc[2][1]);
            acc[3][0] = fma2(zp.x, w3, acc[3][0]); acc[3][1] = fma2(zp.y, w3, acc[3][1]);
        }
        // next tile's wait + barA closes this phase
    }

    // ---- global denominator S (16 k==0 threads hold partials) ----
    if (k == 0) atomicAdd(&sm_S, S_part);
    __syncthreads();   // S complete; agg done before reusing z_s[0]
    const float invS = 1.0f / sm_S;

    float* red = &z_s[0][0];
    {
        const int cb = (tid >> 6) * 1024;
        #pragma unroll
        for (int kk = 0; kk < 4; kk++) {
            float2 lo, hi;
            asm("mov.b64 {%0,%1},%2;":"=f"(lo.x),"=f"(lo.y):"l"(acc[kk][0]));
            asm("mov.b64 {%0,%1},%2;":"=f"(hi.x),"=f"(hi.y):"l"(acc[kk][1]));
            *(float4*)&red[cb + (kg4 + kk) * 64 + dg4] = make_float4(lo.x, lo.y, hi.x, hi.y);
        }
    }
    __syncthreads();

    // ---- final sum + beta_seq + LN + store ----
    {
        const int c4 = tid * 4;
        const int kk = tid >> 4;
        const int d0 = (tid & 15) * 4;
        float4 v0 = *(const float4*)&red[c4];
        float4 v1 = *(const float4*)&red[1024 + c4];
        float4 v2 = *(const float4*)&red[2048 + c4];
        float4 v3 = *(const float4*)&red[3072 + c4];
        float4 bs = *(const float4*)&beta_seq[c4];
        float o0 = (v0.x + v1.x + v2.x + v3.x) * invS + bs.x;
        float o1 = (v0.y + v1.y + v2.y + v3.y) * invS + bs.y;
        float o2 = (v0.z + v1.z + v2.z + v3.z) * invS + bs.z;
        float o3 = (v0.w + v1.w + v2.w + v3.w) * invS + bs.w;
        float s  = o0 + o1 + o2 + o3;
        float sq = o0 * o0 + o1 * o1 + o2 * o2 + o3 * o3;
        #pragma unroll
        for (int m = 8; m; m >>= 1) {
            s  += __shfl_xor_sync(~0u, s,  m);
            sq += __shfl_xor_sync(~0u, sq, m);
        }
        float mean = s * (1.f / 64.f);
        float var  = sq * (1.f / 64.f) - mean * mean;
        float r    = rsqrtf(var + EPSV);
        float4 g4 = *(const float4*)&gamma[4 * 64 + d0];
        float4 b4 = *(const float4*)&beta[4 * 64 + d0];
        float4 ov;
        ov.x = (o0 - mean) * r * g4.x + b4.x;
        ov.y = (o1 - mean) * r * g4.y + b4.y;
        ov.z = (o2 - mean) * r * g4.z + b4.z;
        ov.w = (o3 - mean) * r * g4.w + b4.w;
        *(float4*)&out[((size_t)b * 16 + kk) * 64 + d0] = ov;
    }
}

extern "C" void kernel_launch(void* const* d_in, const int* in_sizes, int n_in,
                              void* d_out, int out_size)
{
    const float* z        = (const float*)d_in[0];
    const float* prot     = (const float*)d_in[1];
    const float* alphas   = (const float*)d_in[2];
    const float* b_bias   = (const float*)d_in[3];
    const float* W        = (const float*)d_in[4];
    // d_in[5] = Wb: softmax-invariant constant, unused.
    const float* gamma    = (const float*)d_in[6];
    const float* beta     = (const float*)d_in[7];
    const float* beta_seq = (const float*)d_in[8];
    float* out = (float*)d_out;

    const int T = in_sizes[2] / 64;
    const int B = in_sizes[0] / (T * 64);

    setup_kernel<<<1, 512>>>(prot, gamma, beta);
    dse_main_kernel<<<B, 256>>>(z, alphas, b_bias, W, gamma, beta, beta_seq, out);
}